// round 1
// baseline (speedup 1.0000x reference)
#include <cuda_runtime.h>
#include <cuda_bf16.h>
#include <cstddef>

#define N_NODES 50000
#define N_EDGES 800000
#define ND_IN   64
#define ED_IN   64
#define HID     128

// ---------------- scratch (allocation-free: __device__ globals) ----------------
__device__ float g_msum[(size_t)N_NODES * 256];   // segment sums (max D = 256)
__device__ float g_deg [N_NODES];                 // in-degree of v (shared by both layers)
__device__ float g_hn1 [(size_t)N_NODES * HID];   // layer-1 node output
__device__ float g_he1 [(size_t)N_EDGES * HID];   // layer-1 edge output

// ---------------- degree ----------------
__global__ void deg_kernel(const int* __restrict__ v) {
    int e = blockIdx.x * blockDim.x + threadIdx.x;
    if (e < N_EDGES) atomicAdd(&g_deg[v[e]], 1.0f);
}

// ---------------- scatter: msum[v] += concat(hn[u], he[e]) ----------------
// one warp per edge; lanes stride the feature dims (coalesced)
template <int DN, int DE>
__global__ void scatter_kernel(const float* __restrict__ hn,
                               const float* __restrict__ he,
                               const int* __restrict__ u,
                               const int* __restrict__ v) {
    constexpr int D = DN + DE;
    int gtid = blockIdx.x * blockDim.x + threadIdx.x;
    int edge = gtid >> 5;
    int lane = gtid & 31;
    if (edge >= N_EDGES) return;
    int un = u[edge];
    int vn = v[edge];
    const float* srcn = hn + (size_t)un * DN;
    const float* srce = he + (size_t)edge * DE;
    float* dst = g_msum + (size_t)vn * D;
    #pragma unroll
    for (int i = 0; i < DN / 32; i++)
        atomicAdd(&dst[lane + 32 * i], srcn[lane + 32 * i]);
    #pragma unroll
    for (int i = 0; i < DE / 32; i++)
        atomicAdd(&dst[DN + lane + 32 * i], srce[lane + 32 * i]);
}

// ---------------- node apply: out = relu(concat(hn, msum/deg) @ W + b) ----------------
// 128 threads (one output column each), 4 nodes per block
template <int KN, int KM>
__global__ void node_apply_kernel(const float* __restrict__ hn,
                                  const float* __restrict__ W,
                                  const float* __restrict__ b,
                                  float* __restrict__ out) {
    constexpr int K = KN + KM;
    constexpr int NPB = 4;
    __shared__ float xs[NPB][K];
    int n0 = blockIdx.x * NPB;
    int tid = threadIdx.x;  // 0..127

    for (int i = tid; i < NPB * K; i += 128) {
        int ni = i / K;
        int k  = i % K;
        int n  = n0 + ni;
        float val;
        if (k < KN) {
            val = hn[(size_t)n * KN + k];
        } else {
            float d = fmaxf(g_deg[n], 1.0f);
            val = g_msum[(size_t)n * KM + (k - KN)] / d;
        }
        xs[ni][k] = val;
    }
    __syncthreads();

    float acc[NPB];
    float bias = b[tid];
    #pragma unroll
    for (int i = 0; i < NPB; i++) acc[i] = bias;

    #pragma unroll 4
    for (int k = 0; k < K; k++) {
        float w = W[k * HID + tid];
        #pragma unroll
        for (int i = 0; i < NPB; i++) acc[i] += xs[i][k] * w;
    }
    #pragma unroll
    for (int i = 0; i < NPB; i++)
        out[(size_t)(n0 + i) * HID + tid] = fmaxf(acc[i], 0.0f);
}

// ---------------- edge apply: out[e] = relu(concat(hn[u], hn[v]) @ W + b) ----------------
// K = 256, 128 outputs. Block = 128 threads = 2 edge-groups x 64 j-threads.
// 16 edges/block; each thread: 8 edges x 2 columns = 16 accumulators.
__global__ void edge_apply_kernel(const float* __restrict__ hn,
                                  const float* __restrict__ W,
                                  const float* __restrict__ b,
                                  const int* __restrict__ u,
                                  const int* __restrict__ v,
                                  float* __restrict__ out) {
    constexpr int EPB = 16;
    constexpr int K = 2 * HID;  // 256
    __shared__ float xs[EPB][K];
    int e0 = blockIdx.x * EPB;
    int tid = threadIdx.x;  // 0..127

    // cooperative gather: xs[e][0:128] = hn[u[e]], xs[e][128:256] = hn[v[e]]
    // 16 edges * 64 float4 chunks = 1024 float4; 128 threads -> 8 each
    for (int idx = tid; idx < EPB * (K / 4); idx += 128) {
        int e = idx >> 6;          // 64 float4 per edge
        int c = idx & 63;
        int edge = e0 + e;
        int node = (c < 32) ? u[edge] : v[edge];
        float4 val = *(const float4*)(hn + (size_t)node * HID + (size_t)(c & 31) * 4);
        *(float4*)(&xs[e][c * 4]) = val;
    }
    __syncthreads();

    int grp = tid >> 6;    // edge group 0/1
    int jt  = tid & 63;    // output-column thread (owns j=jt and j=jt+64)
    float b0 = b[jt], b1 = b[jt + 64];
    float acc0[8], acc1[8];
    #pragma unroll
    for (int i = 0; i < 8; i++) { acc0[i] = b0; acc1[i] = b1; }

    const float (*x8)[K] = &xs[grp * 8];

    #pragma unroll 4
    for (int k = 0; k < K; k++) {
        float wa = W[k * HID + jt];
        float wb = W[k * HID + jt + 64];
        #pragma unroll
        for (int i = 0; i < 8; i++) {
            float x = x8[i][k];
            acc0[i] += x * wa;
            acc1[i] += x * wb;
        }
    }
    #pragma unroll
    for (int i = 0; i < 8; i++) {
        size_t e = (size_t)(e0 + grp * 8 + i);
        out[e * HID + jt]      = fmaxf(acc0[i], 0.0f);
        out[e * HID + jt + 64] = fmaxf(acc1[i], 0.0f);
    }
}

// ---------------- launch ----------------
extern "C" void kernel_launch(void* const* d_in, const int* in_sizes, int n_in,
                              void* d_out, int out_size) {
    const float* nfeats = (const float*)d_in[0];
    const float* efeats = (const float*)d_in[1];
    const float* W1a_w  = (const float*)d_in[2];
    const float* W1a_b  = (const float*)d_in[3];
    const float* W1e_w  = (const float*)d_in[4];
    const float* W1e_b  = (const float*)d_in[5];
    const float* W2a_w  = (const float*)d_in[6];
    const float* W2a_b  = (const float*)d_in[7];
    const float* W2e_w  = (const float*)d_in[8];
    const float* W2e_b  = (const float*)d_in[9];
    const int*   u      = (const int*)d_in[10];
    const int*   v      = (const int*)d_in[11];

    float* out   = (float*)d_out;
    float* hn2   = out;                              // [N, 128]
    float* he2   = out + (size_t)N_NODES * HID;      // [E, 128]

    void *p_msum, *p_deg;
    cudaGetSymbolAddress(&p_msum, g_msum);
    cudaGetSymbolAddress(&p_deg,  g_deg);

    float* hn1; float* he1;
    { void* p; cudaGetSymbolAddress(&p, g_hn1); hn1 = (float*)p; }
    { void* p; cudaGetSymbolAddress(&p, g_he1); he1 = (float*)p; }

    // ---- init ----
    cudaMemsetAsync(p_deg, 0, sizeof(float) * N_NODES, 0);
    cudaMemsetAsync(p_msum, 0, sizeof(float) * (size_t)N_NODES * 256, 0);
    deg_kernel<<<(N_EDGES + 255) / 256, 256>>>(v);

    // ---- layer 1 ----
    scatter_kernel<ND_IN, ED_IN><<<(N_EDGES * 32) / 256, 256>>>(nfeats, efeats, u, v);
    node_apply_kernel<ND_IN, ND_IN + ED_IN><<<N_NODES / 4, 128>>>(nfeats, W1a_w, W1a_b, hn1);
    edge_apply_kernel<<<N_EDGES / 16, 128>>>(hn1, W1e_w, W1e_b, u, v, he1);

    // ---- layer 2 ----
    cudaMemsetAsync(p_msum, 0, sizeof(float) * (size_t)N_NODES * 256, 0);
    scatter_kernel<HID, HID><<<(N_EDGES * 32) / 256, 256>>>(hn1, he1, u, v);
    node_apply_kernel<HID, 2 * HID><<<N_NODES / 4, 128>>>(hn1, W2a_w, W2a_b, hn2);
    edge_apply_kernel<<<N_EDGES / 16, 128>>>(hn2, W2e_w, W2e_b, u, v, he2);
}

// round 2
// speedup vs baseline: 2.4109x; 2.4109x over previous
#include <cuda_runtime.h>
#include <cuda_bf16.h>
#include <cstddef>

#define N_NODES 50000
#define N_EDGES 800000
#define ND_IN   64
#define ED_IN   64
#define HID     128

// ---------------- scratch (allocation-free: __device__ globals) ----------------
__device__ float g_msum[(size_t)N_NODES * 256];   // segment sums (L1: stride 128, L2: stride 256)
__device__ float g_deg [N_NODES];                 // in-degree of v (shared by both layers)
__device__ float g_hn1 [(size_t)N_NODES * HID];   // layer-1 node output
__device__ float g_P   [(size_t)N_NODES * HID];   // hn @ We_top  (per-node edge projection)
__device__ float g_Q   [(size_t)N_NODES * HID];   // hn @ We_bot

__device__ __forceinline__ float4 relu4(float4 a) {
    a.x = fmaxf(a.x, 0.f); a.y = fmaxf(a.y, 0.f);
    a.z = fmaxf(a.z, 0.f); a.w = fmaxf(a.w, 0.f);
    return a;
}

// ---------------- degree ----------------
__global__ void deg_kernel(const int* __restrict__ v) {
    int e = blockIdx.x * blockDim.x + threadIdx.x;
    if (e < N_EDGES) atomicAdd(&g_deg[v[e]], 1.0f);
}

// ---------------- layer-1 scatter: msum[v] (stride 128) += concat(nfeats[u], efeats[e]) ----------------
__global__ void scatter1_kernel(const float* __restrict__ nf,
                                const float* __restrict__ ef,
                                const int* __restrict__ u,
                                const int* __restrict__ v) {
    int gtid = blockIdx.x * blockDim.x + threadIdx.x;
    int e = gtid >> 5;
    int lane = gtid & 31;
    if (e >= N_EDGES) return;
    int un = u[e], vn = v[e];
    const float* srcn = nf + (size_t)un * ND_IN;
    const float* srce = ef + (size_t)e * ED_IN;
    float* dst = g_msum + (size_t)vn * 128;
    atomicAdd(&dst[lane],          srcn[lane]);
    atomicAdd(&dst[lane + 32],     srcn[lane + 32]);
    atomicAdd(&dst[64 + lane],     srce[lane]);
    atomicAdd(&dst[64 + lane + 32], srce[lane + 32]);
}

// ---------------- node apply: out = relu(concat(hn, msum/deg) @ W + b) ----------------
// 16 nodes/block, 128 threads = 2 node-groups x 64 col-threads, 8 nodes x 2 cols per thread
template <int KN, int KM>
__global__ void node_apply_kernel(const float* __restrict__ hn,
                                  const float* __restrict__ W,
                                  const float* __restrict__ b,
                                  float* __restrict__ out) {
    constexpr int K = KN + KM;
    constexpr int NPB = 16;
    __shared__ float xs[NPB][K];
    int n0 = blockIdx.x * NPB;
    int tid = threadIdx.x;

    for (int i = tid; i < NPB * K; i += 128) {
        int ni = i / K;
        int k  = i % K;
        int n  = n0 + ni;
        float val;
        if (k < KN) {
            val = hn[(size_t)n * KN + k];
        } else {
            float d = fmaxf(g_deg[n], 1.0f);
            val = g_msum[(size_t)n * KM + (k - KN)] / d;
        }
        xs[ni][k] = val;
    }
    __syncthreads();

    int grp = tid >> 6;
    int jt  = tid & 63;
    float b0 = b[jt], b1 = b[jt + 64];
    float a0[8], a1[8];
    #pragma unroll
    for (int i = 0; i < 8; i++) { a0[i] = b0; a1[i] = b1; }

    const float (*x8)[K] = &xs[grp * 8];
    #pragma unroll 4
    for (int k = 0; k < K; k++) {
        float w0 = W[k * HID + jt];
        float w1 = W[k * HID + jt + 64];
        #pragma unroll
        for (int i = 0; i < 8; i++) {
            float x = x8[i][k];
            a0[i] += x * w0;
            a1[i] += x * w1;
        }
    }
    #pragma unroll
    for (int i = 0; i < 8; i++) {
        size_t n = (size_t)(n0 + grp * 8 + i);
        out[n * HID + jt]      = fmaxf(a0[i], 0.0f);
        out[n * HID + jt + 64] = fmaxf(a1[i], 0.0f);
    }
}

// ---------------- P/Q projection: P = hn @ W[0:128,:], Q = hn @ W[128:256,:] ----------------
// 16 nodes/block, each thread: 8 nodes x (2 P-cols + 2 Q-cols) = 32 accumulators
__global__ void pq_gemm_kernel(const float* __restrict__ hn,
                               const float* __restrict__ W,  // [256,128] row-major
                               float* __restrict__ P,
                               float* __restrict__ Q) {
    constexpr int NPB = 16;
    __shared__ float xs[NPB][HID];
    int n0 = blockIdx.x * NPB;
    int tid = threadIdx.x;

    for (int i = tid; i < NPB * (HID / 4); i += 128) {
        int ni = i >> 5;
        int c  = i & 31;
        *(float4*)&xs[ni][c * 4] =
            *(const float4*)(hn + (size_t)(n0 + ni) * HID + c * 4);
    }
    __syncthreads();

    int grp = tid >> 6;
    int jt  = tid & 63;
    float p0[8], p1[8], q0[8], q1[8];
    #pragma unroll
    for (int i = 0; i < 8; i++) { p0[i] = p1[i] = q0[i] = q1[i] = 0.0f; }

    const float (*x8)[HID] = &xs[grp * 8];
    #pragma unroll 2
    for (int k = 0; k < HID; k++) {
        float wt0 = W[k * HID + jt];
        float wt1 = W[k * HID + jt + 64];
        float wb0 = W[(k + HID) * HID + jt];
        float wb1 = W[(k + HID) * HID + jt + 64];
        #pragma unroll
        for (int i = 0; i < 8; i++) {
            float x = x8[i][k];
            p0[i] += x * wt0;
            p1[i] += x * wt1;
            q0[i] += x * wb0;
            q1[i] += x * wb1;
        }
    }
    #pragma unroll
    for (int i = 0; i < 8; i++) {
        size_t n = (size_t)(n0 + grp * 8 + i);
        P[n * HID + jt]      = p0[i];
        P[n * HID + jt + 64] = p1[i];
        Q[n * HID + jt]      = q0[i];
        Q[n * HID + jt + 64] = q1[i];
    }
}

// ---------------- layer-1 fused edge: he1 = relu(P[u]+Q[v]+b) computed in registers,
// scattered straight into msum2 (stride 256) along with hn1[u]; he1 never stored ----------------
__global__ void edge1_fused_kernel(const int* __restrict__ u,
                                   const int* __restrict__ v,
                                   const float* __restrict__ be) {
    int gtid = blockIdx.x * blockDim.x + threadIdx.x;
    int e = gtid >> 5;
    int lane = gtid & 31;
    if (e >= N_EDGES) return;
    int un = u[e], vn = v[e];
    int c = lane * 4;

    float4 p  = *(const float4*)&g_P[(size_t)un * HID + c];
    float4 q  = *(const float4*)&g_Q[(size_t)vn * HID + c];
    float4 bb = *(const float4*)&be[c];
    float4 h;
    h.x = fmaxf(p.x + q.x + bb.x, 0.f);
    h.y = fmaxf(p.y + q.y + bb.y, 0.f);
    h.z = fmaxf(p.z + q.z + bb.z, 0.f);
    h.w = fmaxf(p.w + q.w + bb.w, 0.f);

    float4 hu = *(const float4*)&g_hn1[(size_t)un * HID + c];

    float* dst = g_msum + (size_t)vn * 256;
    atomicAdd(&dst[c + 0], hu.x);
    atomicAdd(&dst[c + 1], hu.y);
    atomicAdd(&dst[c + 2], hu.z);
    atomicAdd(&dst[c + 3], hu.w);
    atomicAdd(&dst[128 + c + 0], h.x);
    atomicAdd(&dst[128 + c + 1], h.y);
    atomicAdd(&dst[128 + c + 2], h.z);
    atomicAdd(&dst[128 + c + 3], h.w);
}

// ---------------- layer-2 edge: he2 = relu(P[u]+Q[v]+b) -> out ----------------
__global__ void edge2_kernel(const int* __restrict__ u,
                             const int* __restrict__ v,
                             const float* __restrict__ be,
                             float* __restrict__ he2) {
    int gtid = blockIdx.x * blockDim.x + threadIdx.x;
    int e = gtid >> 5;
    int lane = gtid & 31;
    if (e >= N_EDGES) return;
    int un = u[e], vn = v[e];
    int c = lane * 4;

    float4 p  = *(const float4*)&g_P[(size_t)un * HID + c];
    float4 q  = *(const float4*)&g_Q[(size_t)vn * HID + c];
    float4 bb = *(const float4*)&be[c];
    float4 h;
    h.x = fmaxf(p.x + q.x + bb.x, 0.f);
    h.y = fmaxf(p.y + q.y + bb.y, 0.f);
    h.z = fmaxf(p.z + q.z + bb.z, 0.f);
    h.w = fmaxf(p.w + q.w + bb.w, 0.f);
    *(float4*)&he2[(size_t)e * HID + c] = h;
}

// ---------------- launch ----------------
extern "C" void kernel_launch(void* const* d_in, const int* in_sizes, int n_in,
                              void* d_out, int out_size) {
    const float* nfeats = (const float*)d_in[0];
    const float* efeats = (const float*)d_in[1];
    const float* W1a_w  = (const float*)d_in[2];
    const float* W1a_b  = (const float*)d_in[3];
    const float* W1e_w  = (const float*)d_in[4];
    const float* W1e_b  = (const float*)d_in[5];
    const float* W2a_w  = (const float*)d_in[6];
    const float* W2a_b  = (const float*)d_in[7];
    const float* W2e_w  = (const float*)d_in[8];
    const float* W2e_b  = (const float*)d_in[9];
    const int*   u      = (const int*)d_in[10];
    const int*   v      = (const int*)d_in[11];

    float* out = (float*)d_out;
    float* hn2 = out;                          // [N, 128]
    float* he2 = out + (size_t)N_NODES * HID;  // [E, 128]

    void *p_msum, *p_deg, *p_hn1, *p_P, *p_Q;
    cudaGetSymbolAddress(&p_msum, g_msum);
    cudaGetSymbolAddress(&p_deg,  g_deg);
    cudaGetSymbolAddress(&p_hn1,  g_hn1);
    cudaGetSymbolAddress(&p_P,    g_P);
    cudaGetSymbolAddress(&p_Q,    g_Q);
    float* hn1 = (float*)p_hn1;
    float* P   = (float*)p_P;
    float* Q   = (float*)p_Q;

    const int WARP_BLOCKS = (N_EDGES * 32) / 256;  // 100000

    // ---- init + layer 1 aggregate ----
    cudaMemsetAsync(p_deg, 0, sizeof(float) * N_NODES, 0);
    cudaMemsetAsync(p_msum, 0, sizeof(float) * (size_t)N_NODES * 128, 0);
    deg_kernel<<<(N_EDGES + 255) / 256, 256>>>(v);
    scatter1_kernel<<<WARP_BLOCKS, 256>>>(nfeats, efeats, u, v);

    // ---- layer 1 node apply + edge projection ----
    node_apply_kernel<ND_IN, ND_IN + ED_IN><<<N_NODES / 16, 128>>>(nfeats, W1a_w, W1a_b, hn1);
    pq_gemm_kernel<<<N_NODES / 16, 128>>>(hn1, W1e_w, P, Q);

    // ---- fused layer-1 edge + layer-2 aggregate ----
    cudaMemsetAsync(p_msum, 0, sizeof(float) * (size_t)N_NODES * 256, 0);
    edge1_fused_kernel<<<WARP_BLOCKS, 256>>>(u, v, W1e_b);

    // ---- layer 2 ----
    node_apply_kernel<HID, 2 * HID><<<N_NODES / 16, 128>>>(hn1, W2a_w, W2a_b, hn2);
    pq_gemm_kernel<<<N_NODES / 16, 128>>>(hn2, W2e_w, P, Q);
    edge2_kernel<<<WARP_BLOCKS, 256>>>(u, v, W2e_b, he2);
}

// round 3
// speedup vs baseline: 3.4151x; 1.4166x over previous
#include <cuda_runtime.h>
#include <cuda_bf16.h>
#include <cstddef>

#define N_NODES 50000
#define N_EDGES 800000
#define ND_IN   64
#define ED_IN   64
#define HID     128

typedef unsigned long long ull;

// ---------------- scratch (allocation-free: __device__ globals) ----------------
__device__ float g_msum1[(size_t)N_NODES * 128];  // layer-1 segment sums
__device__ float g_msum2[(size_t)N_NODES * 256];  // layer-2 segment sums
__device__ float g_deg  [N_NODES];                // in-degree of v
__device__ float g_hn1  [(size_t)N_NODES * HID];  // layer-1 node output
__device__ float g_P    [(size_t)N_NODES * HID];  // hn @ We_top
__device__ float g_Q    [(size_t)N_NODES * HID];  // hn @ We_bot

// ---------------- packed f32x2 helpers ----------------
__device__ __forceinline__ ull pk2(float x, float y) {
    ull r; asm("mov.b64 %0, {%1, %2};" : "=l"(r) : "f"(x), "f"(y)); return r;
}
__device__ __forceinline__ void upk2(ull p, float& x, float& y) {
    asm("mov.b64 {%0, %1}, %2;" : "=f"(x), "=f"(y) : "l"(p));
}
#define FFMA2(d, a, b, c) \
    asm("fma.rn.f32x2 %0, %1, %2, %3;" : "=l"(d) : "l"(a), "l"(b), "l"(c))

// ---------------- vector fp32 reduction (sm_90+) ----------------
__device__ __forceinline__ void red_add_v4(float* addr, float4 v) {
    asm volatile("red.global.add.v4.f32 [%0], {%1, %2, %3, %4};"
                 :: "l"(addr), "f"(v.x), "f"(v.y), "f"(v.z), "f"(v.w) : "memory");
}

// ---------------- layer-1 scatter (+degree): msum1[v] += concat(nf[u], ef[e]) ----------------
// one warp per edge; lane handles 4 floats: 1 load + 1 red.v4
__global__ void scatter1_kernel(const float* __restrict__ nf,
                                const float* __restrict__ ef,
                                const int* __restrict__ u,
                                const int* __restrict__ v) {
    int gtid = blockIdx.x * blockDim.x + threadIdx.x;
    int e = gtid >> 5;
    int lane = gtid & 31;
    if (e >= N_EDGES) return;
    int un = u[e], vn = v[e];
    if (lane == 0) atomicAdd(&g_deg[vn], 1.0f);
    int c = lane * 4;
    float4 val;
    if (c < ND_IN) val = *(const float4*)&nf[(size_t)un * ND_IN + c];
    else           val = *(const float4*)&ef[(size_t)e * ED_IN + (c - ND_IN)];
    red_add_v4(&g_msum1[(size_t)vn * 128 + c], val);
}

// ---------------- node apply: out = relu(concat(hn, msum/deg) @ W + b) ----------------
// NPB=16 nodes/block, 128 threads = 2 groups x 64 col-threads.
// Transposed shared x[k][node] (stride 18: 8B-aligned, low-conflict).
// Each thread: 4 node-pairs x 2 cols via packed FFMA2.
template <int KN, int KM>
__global__ void __launch_bounds__(128)
node_apply_kernel(const float* __restrict__ hn,
                  const float* __restrict__ msum,
                  const float* __restrict__ W,
                  const float* __restrict__ b,
                  float* __restrict__ out) {
    constexpr int K = KN + KM;
    constexpr int NPB = 16;
    __shared__ float xs[K][18];
    int n0 = blockIdx.x * NPB;
    int tid = threadIdx.x;

    for (int idx = tid; idx < NPB * K; idx += 128) {
        int ni = idx / K;
        int k  = idx % K;
        int n  = n0 + ni;
        float val;
        if (k < KN) {
            val = hn[(size_t)n * KN + k];
        } else {
            float d = fmaxf(g_deg[n], 1.0f);
            val = msum[(size_t)n * KM + (k - KN)] / d;
        }
        xs[k][ni] = val;
    }
    __syncthreads();

    int grp = tid >> 6;    // node sub-group: 8 nodes = 4 pairs
    int jt  = tid & 63;    // owns cols jt, jt+64
    float b0 = b[jt], b1 = b[jt + 64];
    ull a0[4], a1[4];
    #pragma unroll
    for (int i = 0; i < 4; i++) { a0[i] = pk2(b0, b0); a1[i] = pk2(b1, b1); }

    const float* Wj = W + jt;
    #pragma unroll 4
    for (int k = 0; k < K; k++) {
        float w0 = Wj[k * HID];
        float w1 = Wj[k * HID + 64];
        ull w0d = pk2(w0, w0);
        ull w1d = pk2(w1, w1);
        ull xp[4];
        #pragma unroll
        for (int i = 0; i < 4; i++)
            xp[i] = *(const ull*)&xs[k][grp * 8 + 2 * i];
        #pragma unroll
        for (int i = 0; i < 4; i++) {
            FFMA2(a0[i], xp[i], w0d, a0[i]);
            FFMA2(a1[i], xp[i], w1d, a1[i]);
        }
    }
    #pragma unroll
    for (int i = 0; i < 4; i++) {
        float x0, x1, y0, y1;
        upk2(a0[i], x0, x1);
        upk2(a1[i], y0, y1);
        size_t n = (size_t)(n0 + grp * 8 + 2 * i);
        out[n * HID + jt]            = fmaxf(x0, 0.0f);
        out[(n + 1) * HID + jt]      = fmaxf(x1, 0.0f);
        out[n * HID + jt + 64]       = fmaxf(y0, 0.0f);
        out[(n + 1) * HID + jt + 64] = fmaxf(y1, 0.0f);
    }
}

// ---------------- P/Q projection: P = hn @ W[0:128,:], Q = hn @ W[128:256,:] ----------------
// Same structure; 4 node-pairs x (2 P-cols + 2 Q-cols) = 16 packed accumulators.
__global__ void __launch_bounds__(128)
pq_gemm_kernel(const float* __restrict__ hn,
               const float* __restrict__ W,   // [256,128] row-major
               float* __restrict__ P,
               float* __restrict__ Q) {
    constexpr int NPB = 16;
    __shared__ float xs[HID][18];
    int n0 = blockIdx.x * NPB;
    int tid = threadIdx.x;

    for (int idx = tid; idx < NPB * HID; idx += 128) {
        int ni = idx >> 7;
        int k  = idx & 127;
        xs[k][ni] = hn[(size_t)(n0 + ni) * HID + k];
    }
    __syncthreads();

    int grp = tid >> 6;
    int jt  = tid & 63;
    ull p0[4], p1[4], q0[4], q1[4];
    #pragma unroll
    for (int i = 0; i < 4; i++) { p0[i] = p1[i] = q0[i] = q1[i] = 0ull; }

    const float* Wj = W + jt;
    #pragma unroll 2
    for (int k = 0; k < HID; k++) {
        float wt0 = Wj[k * HID];
        float wt1 = Wj[k * HID + 64];
        float wb0 = Wj[(k + HID) * HID];
        float wb1 = Wj[(k + HID) * HID + 64];
        ull wt0d = pk2(wt0, wt0);
        ull wt1d = pk2(wt1, wt1);
        ull wb0d = pk2(wb0, wb0);
        ull wb1d = pk2(wb1, wb1);
        ull xp[4];
        #pragma unroll
        for (int i = 0; i < 4; i++)
            xp[i] = *(const ull*)&xs[k][grp * 8 + 2 * i];
        #pragma unroll
        for (int i = 0; i < 4; i++) {
            FFMA2(p0[i], xp[i], wt0d, p0[i]);
            FFMA2(p1[i], xp[i], wt1d, p1[i]);
            FFMA2(q0[i], xp[i], wb0d, q0[i]);
            FFMA2(q1[i], xp[i], wb1d, q1[i]);
        }
    }
    #pragma unroll
    for (int i = 0; i < 4; i++) {
        float x0, x1;
        size_t n = (size_t)(n0 + grp * 8 + 2 * i);
        upk2(p0[i], x0, x1); P[n * HID + jt]      = x0; P[(n + 1) * HID + jt]      = x1;
        upk2(p1[i], x0, x1); P[n * HID + jt + 64] = x0; P[(n + 1) * HID + jt + 64] = x1;
        upk2(q0[i], x0, x1); Q[n * HID + jt]      = x0; Q[(n + 1) * HID + jt]      = x1;
        upk2(q1[i], x0, x1); Q[n * HID + jt + 64] = x0; Q[(n + 1) * HID + jt + 64] = x1;
    }
}

// ---------------- layer-1 fused edge: he1 = relu(P[u]+Q[v]+b) in registers,
// scattered into msum2 along with hn1[u]; he1 never materialized ----------------
__global__ void edge1_fused_kernel(const int* __restrict__ u,
                                   const int* __restrict__ v,
                                   const float* __restrict__ be) {
    int gtid = blockIdx.x * blockDim.x + threadIdx.x;
    int e = gtid >> 5;
    int lane = gtid & 31;
    if (e >= N_EDGES) return;
    int un = u[e], vn = v[e];
    int c = lane * 4;

    float4 p  = *(const float4*)&g_P[(size_t)un * HID + c];
    float4 q  = *(const float4*)&g_Q[(size_t)vn * HID + c];
    float4 bb = *(const float4*)&be[c];
    float4 h;
    h.x = fmaxf(p.x + q.x + bb.x, 0.f);
    h.y = fmaxf(p.y + q.y + bb.y, 0.f);
    h.z = fmaxf(p.z + q.z + bb.z, 0.f);
    h.w = fmaxf(p.w + q.w + bb.w, 0.f);

    float4 hu = *(const float4*)&g_hn1[(size_t)un * HID + c];

    float* dst = g_msum2 + (size_t)vn * 256;
    red_add_v4(&dst[c], hu);
    red_add_v4(&dst[128 + c], h);
}

// ---------------- layer-2 edge: he2 = relu(P[u]+Q[v]+b) -> out ----------------
__global__ void edge2_kernel(const int* __restrict__ u,
                             const int* __restrict__ v,
                             const float* __restrict__ be,
                             float* __restrict__ he2) {
    int gtid = blockIdx.x * blockDim.x + threadIdx.x;
    int e = gtid >> 5;
    int lane = gtid & 31;
    if (e >= N_EDGES) return;
    int un = u[e], vn = v[e];
    int c = lane * 4;

    float4 p  = *(const float4*)&g_P[(size_t)un * HID + c];
    float4 q  = *(const float4*)&g_Q[(size_t)vn * HID + c];
    float4 bb = *(const float4*)&be[c];
    float4 h;
    h.x = fmaxf(p.x + q.x + bb.x, 0.f);
    h.y = fmaxf(p.y + q.y + bb.y, 0.f);
    h.z = fmaxf(p.z + q.z + bb.z, 0.f);
    h.w = fmaxf(p.w + q.w + bb.w, 0.f);
    *(float4*)&he2[(size_t)e * HID + c] = h;
}

// ---------------- launch ----------------
extern "C" void kernel_launch(void* const* d_in, const int* in_sizes, int n_in,
                              void* d_out, int out_size) {
    const float* nfeats = (const float*)d_in[0];
    const float* efeats = (const float*)d_in[1];
    const float* W1a_w  = (const float*)d_in[2];
    const float* W1a_b  = (const float*)d_in[3];
    const float* W1e_w  = (const float*)d_in[4];
    const float* W1e_b  = (const float*)d_in[5];
    const float* W2a_w  = (const float*)d_in[6];
    const float* W2a_b  = (const float*)d_in[7];
    const float* W2e_w  = (const float*)d_in[8];
    const float* W2e_b  = (const float*)d_in[9];
    const int*   u      = (const int*)d_in[10];
    const int*   v      = (const int*)d_in[11];

    float* out = (float*)d_out;
    float* hn2 = out;                          // [N, 128]
    float* he2 = out + (size_t)N_NODES * HID;  // [E, 128]

    void *p_m1, *p_m2, *p_deg, *p_hn1, *p_P, *p_Q;
    cudaGetSymbolAddress(&p_m1,  g_msum1);
    cudaGetSymbolAddress(&p_m2,  g_msum2);
    cudaGetSymbolAddress(&p_deg, g_deg);
    cudaGetSymbolAddress(&p_hn1, g_hn1);
    cudaGetSymbolAddress(&p_P,   g_P);
    cudaGetSymbolAddress(&p_Q,   g_Q);
    float* msum1 = (float*)p_m1;
    float* msum2 = (float*)p_m2;
    float* hn1   = (float*)p_hn1;
    float* P     = (float*)p_P;
    float* Q     = (float*)p_Q;

    const int WARP_BLOCKS = (N_EDGES * 32) / 256;  // 100000

    // ---- zero all accumulators once, up front ----
    cudaMemsetAsync(p_deg, 0, sizeof(float) * N_NODES, 0);
    cudaMemsetAsync(p_m1,  0, sizeof(float) * (size_t)N_NODES * 128, 0);
    cudaMemsetAsync(p_m2,  0, sizeof(float) * (size_t)N_NODES * 256, 0);

    // ---- layer 1 ----
    scatter1_kernel<<<WARP_BLOCKS, 256>>>(nfeats, efeats, u, v);
    node_apply_kernel<ND_IN, ND_IN + ED_IN><<<N_NODES / 16, 128>>>(nfeats, msum1, W1a_w, W1a_b, hn1);
    pq_gemm_kernel<<<N_NODES / 16, 128>>>(hn1, W1e_w, P, Q);
    edge1_fused_kernel<<<WARP_BLOCKS, 256>>>(u, v, W1e_b);

    // ---- layer 2 ----
    node_apply_kernel<HID, 2 * HID><<<N_NODES / 16, 128>>>(hn1, msum2, W2a_w, W2a_b, hn2);
    pq_gemm_kernel<<<N_NODES / 16, 128>>>(hn2, W2e_w, P, Q);
    edge2_kernel<<<WARP_BLOCKS, 256>>>(u, v, W2e_b, he2);
}

// round 4
// speedup vs baseline: 3.5845x; 1.0496x over previous
#include <cuda_runtime.h>
#include <cuda_bf16.h>
#include <cstddef>

#define N_NODES 50000
#define N_EDGES 800000
#define ND_IN   64
#define ED_IN   64
#define HID     128

typedef unsigned long long ull;

// ---------------- scratch (allocation-free: __device__ globals) ----------------
__device__ int   g_cnt   [N_NODES];               // per-dst edge count
__device__ int   g_rowptr[N_NODES + 1];           // CSR row pointers (by dst)
__device__ int   g_cursor[N_NODES];               // fill cursors
__device__ int   g_eu    [N_EDGES];               // src node per CSR slot
__device__ int   g_eid   [N_EDGES];               // original edge id per CSR slot
__device__ float g_msum1[(size_t)N_NODES * 128];  // layer-1 segment sums
__device__ float g_msum2[(size_t)N_NODES * 256];  // layer-2 segment sums
__device__ float g_hn1  [(size_t)N_NODES * HID];  // layer-1 node output
__device__ float g_P    [(size_t)N_NODES * HID];  // hn @ We_top
__device__ float g_Q    [(size_t)N_NODES * HID];  // hn @ We_bot

// ---------------- packed f32x2 helpers ----------------
__device__ __forceinline__ ull pk2(float x, float y) {
    ull r; asm("mov.b64 %0, {%1, %2};" : "=l"(r) : "f"(x), "f"(y)); return r;
}
__device__ __forceinline__ void upk2(ull p, float& x, float& y) {
    asm("mov.b64 {%0, %1}, %2;" : "=f"(x), "=f"(y) : "l"(p));
}
#define FFMA2(d, a, b, c) \
    asm("fma.rn.f32x2 %0, %1, %2, %3;" : "=l"(d) : "l"(a), "l"(b), "l"(c))

// ================= CSR build =================
__global__ void cnt_kernel(const int* __restrict__ v) {
    int e = blockIdx.x * blockDim.x + threadIdx.x;
    if (e < N_EDGES) atomicAdd(&g_cnt[v[e]], 1);
}

// single-block exclusive scan over g_cnt -> g_rowptr (chunked, carry in smem)
__global__ void scan_kernel() {
    __shared__ int warp_sums[8];
    __shared__ int s_carry;
    int tid = threadIdx.x;
    int lane = tid & 31;
    int wrp = tid >> 5;
    if (tid == 0) s_carry = 0;
    __syncthreads();
    for (int base = 0; base < N_NODES; base += 256) {
        int i = base + tid;
        int x = (i < N_NODES) ? g_cnt[i] : 0;
        int vv = x;
        #pragma unroll
        for (int d = 1; d < 32; d <<= 1) {
            int t = __shfl_up_sync(0xffffffffu, vv, d);
            if (lane >= d) vv += t;
        }
        if (lane == 31) warp_sums[wrp] = vv;
        __syncthreads();
        if (tid < 8) {
            int w = warp_sums[tid];
            #pragma unroll
            for (int d = 1; d < 8; d <<= 1) {
                int t = __shfl_up_sync(0xffu, w, d);
                if (tid >= d) w += t;
            }
            warp_sums[tid] = w;
        }
        __syncthreads();
        int incl = vv + (wrp > 0 ? warp_sums[wrp - 1] : 0) + s_carry;
        if (i < N_NODES) g_rowptr[i] = incl - x;
        __syncthreads();
        if (tid == 255) s_carry = incl;
        __syncthreads();
    }
    if (tid == 0) g_rowptr[N_NODES] = s_carry;
}

__global__ void fill_kernel(const int* __restrict__ u, const int* __restrict__ v) {
    int e = blockIdx.x * blockDim.x + threadIdx.x;
    if (e >= N_EDGES) return;
    int pos = atomicAdd(&g_cursor[v[e]], 1);
    g_eu[pos]  = u[e];
    g_eid[pos] = e;
}

// ================= layer-1 aggregation (gather, warp per node) =================
// msum1[v] = sum over incoming edges of concat(nf[u], ef[e])
__global__ void agg1_kernel(const float* __restrict__ nf,
                            const float* __restrict__ ef) {
    int gtid = blockIdx.x * blockDim.x + threadIdx.x;
    int node = gtid >> 5;
    int lane = gtid & 31;
    if (node >= N_NODES) return;
    int beg = g_rowptr[node], end = g_rowptr[node + 1];
    int c = lane * 4;
    float4 acc = make_float4(0.f, 0.f, 0.f, 0.f);
    for (int i = beg; i < end; i++) {
        const float4* src;
        if (lane < 16)
            src = (const float4*)(nf + (size_t)g_eu[i] * ND_IN + c);
        else
            src = (const float4*)(ef + (size_t)g_eid[i] * ED_IN + (c - ND_IN));
        float4 t = *src;
        acc.x += t.x; acc.y += t.y; acc.z += t.z; acc.w += t.w;
    }
    *(float4*)&g_msum1[(size_t)node * 128 + c] = acc;
}

// ================= layer-2 aggregation fused with edge-1 MLP (gather) =================
// msum2[v][0:128]   = sum hn1[u]
// msum2[v][128:256] = sum relu(P[u] + Q[v] + b)   (he1 never materialized)
__global__ void agg2_kernel(const float* __restrict__ be) {
    int gtid = blockIdx.x * blockDim.x + threadIdx.x;
    int node = gtid >> 5;
    int lane = gtid & 31;
    if (node >= N_NODES) return;
    int beg = g_rowptr[node], end = g_rowptr[node + 1];
    int c = lane * 4;

    float4 qb = *(const float4*)&g_Q[(size_t)node * HID + c];
    float4 bb = *(const float4*)&be[c];
    qb.x += bb.x; qb.y += bb.y; qb.z += bb.z; qb.w += bb.w;

    float4 accH = make_float4(0.f, 0.f, 0.f, 0.f);
    float4 accE = make_float4(0.f, 0.f, 0.f, 0.f);
    for (int i = beg; i < end; i++) {
        int un = g_eu[i];
        float4 hu = *(const float4*)&g_hn1[(size_t)un * HID + c];
        float4 p  = *(const float4*)&g_P[(size_t)un * HID + c];
        accH.x += hu.x; accH.y += hu.y; accH.z += hu.z; accH.w += hu.w;
        accE.x += fmaxf(p.x + qb.x, 0.f);
        accE.y += fmaxf(p.y + qb.y, 0.f);
        accE.z += fmaxf(p.z + qb.z, 0.f);
        accE.w += fmaxf(p.w + qb.w, 0.f);
    }
    *(float4*)&g_msum2[(size_t)node * 256 + c]       = accH;
    *(float4*)&g_msum2[(size_t)node * 256 + 128 + c] = accE;
}

// ================= node apply: out = relu(concat(hn, msum/deg) @ W + b) =================
template <int KN, int KM>
__global__ void __launch_bounds__(128)
node_apply_kernel(const float* __restrict__ hn,
                  const float* __restrict__ msum,
                  const float* __restrict__ W,
                  const float* __restrict__ b,
                  float* __restrict__ out) {
    constexpr int K = KN + KM;
    constexpr int NPB = 16;
    __shared__ float xs[K][18];
    int n0 = blockIdx.x * NPB;
    int tid = threadIdx.x;

    for (int idx = tid; idx < NPB * K; idx += 128) {
        int ni = idx / K;
        int k  = idx % K;
        int n  = n0 + ni;
        float val;
        if (k < KN) {
            val = hn[(size_t)n * KN + k];
        } else {
            float d = (float)max(g_rowptr[n + 1] - g_rowptr[n], 1);
            val = msum[(size_t)n * KM + (k - KN)] / d;
        }
        xs[k][ni] = val;
    }
    __syncthreads();

    int grp = tid >> 6;
    int jt  = tid & 63;
    float b0 = b[jt], b1 = b[jt + 64];
    ull a0[4], a1[4];
    #pragma unroll
    for (int i = 0; i < 4; i++) { a0[i] = pk2(b0, b0); a1[i] = pk2(b1, b1); }

    const float* Wj = W + jt;
    #pragma unroll 4
    for (int k = 0; k < K; k++) {
        float w0 = Wj[k * HID];
        float w1 = Wj[k * HID + 64];
        ull w0d = pk2(w0, w0);
        ull w1d = pk2(w1, w1);
        ull xp[4];
        #pragma unroll
        for (int i = 0; i < 4; i++)
            xp[i] = *(const ull*)&xs[k][grp * 8 + 2 * i];
        #pragma unroll
        for (int i = 0; i < 4; i++) {
            FFMA2(a0[i], xp[i], w0d, a0[i]);
            FFMA2(a1[i], xp[i], w1d, a1[i]);
        }
    }
    #pragma unroll
    for (int i = 0; i < 4; i++) {
        float x0, x1, y0, y1;
        upk2(a0[i], x0, x1);
        upk2(a1[i], y0, y1);
        size_t n = (size_t)(n0 + grp * 8 + 2 * i);
        out[n * HID + jt]            = fmaxf(x0, 0.0f);
        out[(n + 1) * HID + jt]      = fmaxf(x1, 0.0f);
        out[n * HID + jt + 64]       = fmaxf(y0, 0.0f);
        out[(n + 1) * HID + jt + 64] = fmaxf(y1, 0.0f);
    }
}

// ================= P/Q projection =================
__global__ void __launch_bounds__(128)
pq_gemm_kernel(const float* __restrict__ hn,
               const float* __restrict__ W,   // [256,128] row-major
               float* __restrict__ P,
               float* __restrict__ Q) {
    constexpr int NPB = 16;
    __shared__ float xs[HID][18];
    int n0 = blockIdx.x * NPB;
    int tid = threadIdx.x;

    for (int idx = tid; idx < NPB * HID; idx += 128) {
        int ni = idx >> 7;
        int k  = idx & 127;
        xs[k][ni] = hn[(size_t)(n0 + ni) * HID + k];
    }
    __syncthreads();

    int grp = tid >> 6;
    int jt  = tid & 63;
    ull p0[4], p1[4], q0[4], q1[4];
    #pragma unroll
    for (int i = 0; i < 4; i++) { p0[i] = p1[i] = q0[i] = q1[i] = 0ull; }

    const float* Wj = W + jt;
    #pragma unroll 2
    for (int k = 0; k < HID; k++) {
        float wt0 = Wj[k * HID];
        float wt1 = Wj[k * HID + 64];
        float wb0 = Wj[(k + HID) * HID];
        float wb1 = Wj[(k + HID) * HID + 64];
        ull wt0d = pk2(wt0, wt0);
        ull wt1d = pk2(wt1, wt1);
        ull wb0d = pk2(wb0, wb0);
        ull wb1d = pk2(wb1, wb1);
        ull xp[4];
        #pragma unroll
        for (int i = 0; i < 4; i++)
            xp[i] = *(const ull*)&xs[k][grp * 8 + 2 * i];
        #pragma unroll
        for (int i = 0; i < 4; i++) {
            FFMA2(p0[i], xp[i], wt0d, p0[i]);
            FFMA2(p1[i], xp[i], wt1d, p1[i]);
            FFMA2(q0[i], xp[i], wb0d, q0[i]);
            FFMA2(q1[i], xp[i], wb1d, q1[i]);
        }
    }
    #pragma unroll
    for (int i = 0; i < 4; i++) {
        float x0, x1;
        size_t n = (size_t)(n0 + grp * 8 + 2 * i);
        upk2(p0[i], x0, x1); P[n * HID + jt]      = x0; P[(n + 1) * HID + jt]      = x1;
        upk2(p1[i], x0, x1); P[n * HID + jt + 64] = x0; P[(n + 1) * HID + jt + 64] = x1;
        upk2(q0[i], x0, x1); Q[n * HID + jt]      = x0; Q[(n + 1) * HID + jt]      = x1;
        upk2(q1[i], x0, x1); Q[n * HID + jt + 64] = x0; Q[(n + 1) * HID + jt + 64] = x1;
    }
}

// ================= layer-2 edge: he2 = relu(P[u]+Q[v]+b) -> out =================
__global__ void edge2_kernel(const int* __restrict__ u,
                             const int* __restrict__ v,
                             const float* __restrict__ be,
                             float* __restrict__ he2) {
    int gtid = blockIdx.x * blockDim.x + threadIdx.x;
    int e = gtid >> 5;
    int lane = gtid & 31;
    if (e >= N_EDGES) return;
    int un = u[e], vn = v[e];
    int c = lane * 4;

    float4 p  = *(const float4*)&g_P[(size_t)un * HID + c];
    float4 q  = *(const float4*)&g_Q[(size_t)vn * HID + c];
    float4 bb = *(const float4*)&be[c];
    float4 h;
    h.x = fmaxf(p.x + q.x + bb.x, 0.f);
    h.y = fmaxf(p.y + q.y + bb.y, 0.f);
    h.z = fmaxf(p.z + q.z + bb.z, 0.f);
    h.w = fmaxf(p.w + q.w + bb.w, 0.f);
    *(float4*)&he2[(size_t)e * HID + c] = h;
}

// ---------------- launch ----------------
extern "C" void kernel_launch(void* const* d_in, const int* in_sizes, int n_in,
                              void* d_out, int out_size) {
    const float* nfeats = (const float*)d_in[0];
    const float* efeats = (const float*)d_in[1];
    const float* W1a_w  = (const float*)d_in[2];
    const float* W1a_b  = (const float*)d_in[3];
    const float* W1e_w  = (const float*)d_in[4];
    const float* W1e_b  = (const float*)d_in[5];
    const float* W2a_w  = (const float*)d_in[6];
    const float* W2a_b  = (const float*)d_in[7];
    const float* W2e_w  = (const float*)d_in[8];
    const float* W2e_b  = (const float*)d_in[9];
    const int*   u      = (const int*)d_in[10];
    const int*   v      = (const int*)d_in[11];

    float* out = (float*)d_out;
    float* hn2 = out;                          // [N, 128]
    float* he2 = out + (size_t)N_NODES * HID;  // [E, 128]

    void *p_cnt, *p_rowptr, *p_cursor, *p_m1, *p_m2, *p_hn1, *p_P, *p_Q;
    cudaGetSymbolAddress(&p_cnt,    g_cnt);
    cudaGetSymbolAddress(&p_rowptr, g_rowptr);
    cudaGetSymbolAddress(&p_cursor, g_cursor);
    cudaGetSymbolAddress(&p_m1,     g_msum1);
    cudaGetSymbolAddress(&p_m2,     g_msum2);
    cudaGetSymbolAddress(&p_hn1,    g_hn1);
    cudaGetSymbolAddress(&p_P,      g_P);
    cudaGetSymbolAddress(&p_Q,      g_Q);
    float* msum1 = (float*)p_m1;
    float* msum2 = (float*)p_m2;
    float* hn1   = (float*)p_hn1;
    float* P     = (float*)p_P;
    float* Q     = (float*)p_Q;

    const int EBLK = (N_EDGES + 255) / 256;             // edge-parallel blocks
    const int WBLK = (N_EDGES * 32 + 255) / 256;        // warp-per-edge blocks
    const int NWBLK = (N_NODES * 32 + 255) / 256;       // warp-per-node blocks

    // ---- CSR build (per replay; inputs fixed, so deterministic sums up to fp order) ----
    cudaMemsetAsync(p_cnt, 0, sizeof(int) * N_NODES, 0);
    cnt_kernel<<<EBLK, 256>>>(v);
    scan_kernel<<<1, 256>>>();
    cudaMemcpyAsync(p_cursor, p_rowptr, sizeof(int) * N_NODES,
                    cudaMemcpyDeviceToDevice, 0);
    fill_kernel<<<EBLK, 256>>>(u, v);

    // ---- layer 1 ----
    agg1_kernel<<<NWBLK, 256>>>(nfeats, efeats);
    node_apply_kernel<ND_IN, ND_IN + ED_IN><<<N_NODES / 16, 128>>>(nfeats, msum1, W1a_w, W1a_b, hn1);
    pq_gemm_kernel<<<N_NODES / 16, 128>>>(hn1, W1e_w, P, Q);

    // ---- layer-2 aggregation (fused layer-1 edge MLP) ----
    agg2_kernel<<<NWBLK, 256>>>(W1e_b);

    // ---- layer 2 ----
    node_apply_kernel<HID, 2 * HID><<<N_NODES / 16, 128>>>(hn1, msum2, W2a_w, W2a_b, hn2);
    pq_gemm_kernel<<<N_NODES / 16, 128>>>(hn2, W2e_w, P, Q);
    edge2_kernel<<<WBLK, 256>>>(u, v, W2e_b, he2);
}